// round 12
// baseline (speedup 1.0000x reference)
#include <cuda_runtime.h>
#include <cuda_fp16.h>
#include <cuda_bf16.h>
#include <cstdint>

#define HDIM 128
#define MAXN 50000
#define MAXE 600000
#define MAXG 128
#define CDIM 10

// ---------------- scratch (no allocations allowed) ----------------
__device__ int      g_is64;
__device__ int      g_cnt[MAXN];
__device__ float    g_dinv[MAXN];
__device__ int      g_ptr[MAXN + 1];
__device__ int      g_pos[MAXN];
__device__ int      g_csrc[MAXE];
__device__ int      g_bsum[128];
__device__ float    g_h[(size_t)MAXN * HDIM];
__device__ __half   g_tmp[(size_t)MAXN * HDIM];
__device__ float    g_pool[MAXG * HDIM];
__device__ float    g_gcnt[MAXG];
__device__ uint32_t g_wth[3][HDIM * 64];   // W^T bf16-hi, packed k-pairs: [n][kp]
__device__ uint32_t g_wtl[3][HDIM * 64];   // W^T bf16-lo

__device__ __forceinline__ int loadIdx(const void* p, long long i, int is64) {
    if (is64) return (int)((const long long*)p)[i];
    return ((const int*)p)[i];
}

// ---------------- fused prep ----------------
__global__ void k_init(const void* ei, int n, int g) {
    int i = blockIdx.x * blockDim.x + threadIdx.x;
    if (i == 0) {
        const int* w = (const int*)ei;
        int all0 = 1;
        for (int j = 0; j < 32; j++) if (w[2 * j + 1] != 0) all0 = 0;
        g_is64 = all0;
    }
    if (i < n) g_cnt[i] = 0;
    if (i < g * HDIM) g_pool[i] = 0.f;
    if (i < g) g_gcnt[i] = 0.f;
}

__global__ void k_deg(const void* ei, int E) {
    int e = blockIdx.x * blockDim.x + threadIdx.x;
    if (e >= E) return;
    int d = loadIdx(ei, (long long)E + e, g_is64);
    atomicAdd(&g_cnt[d], 1);
}

__global__ void k_scan1(int n) {
    __shared__ int s[1024];
    int tid = threadIdx.x;
    int i = blockIdx.x * 1024 + tid;
    int v = (i < n) ? g_cnt[i] : 0;
    if (i < n) g_dinv[i] = rsqrtf((float)(v + 1));   // +1 = self-loop
    s[tid] = v;
    __syncthreads();
    for (int off = 1; off < 1024; off <<= 1) {
        int t = (tid >= off) ? s[tid - off] : 0;
        __syncthreads();
        s[tid] += t;
        __syncthreads();
    }
    if (i < n) g_ptr[i] = s[tid] - v;
    if (tid == 1023) g_bsum[blockIdx.x] = s[tid];
}

__global__ void k_scan23(int n, int nb) {
    __shared__ int carry;
    if (threadIdx.x == 0) {
        int acc = 0;
        for (int b = 0; b < blockIdx.x; b++) acc += g_bsum[b];
        carry = acc;
        if (blockIdx.x == nb - 1) g_ptr[n] = acc + g_bsum[nb - 1];
    }
    __syncthreads();
    int i = blockIdx.x * 1024 + threadIdx.x;
    if (i < n) {
        int p = g_ptr[i] + carry;
        g_ptr[i] = p;
        g_pos[i] = p;
    }
}

__global__ void k_fill(const void* ei, const void* batch, int E, int n) {
    int e = blockIdx.x * blockDim.x + threadIdx.x;
    if (e >= E) return;
    int is64 = g_is64;
    int s = loadIdx(ei, e, is64);
    int d = loadIdx(ei, (long long)E + e, is64);
    int p = atomicAdd(&g_pos[d], 1);
    g_csrc[p] = s;
    if (e < n) {
        int g = loadIdx(batch, e, is64);
        atomicAdd(&g_gcnt[g], 1.0f);
    }
}

// ---------------- W split/transpose ----------------
__global__ void k_wsplit(const float* __restrict__ W1, const float* __restrict__ W2,
                         const float* __restrict__ W3) {
    int i = blockIdx.x * blockDim.x + threadIdx.x;
    if (i >= 3 * HDIM * 64) return;
    int l = i >> 13, r = i & 8191;
    int n = r >> 6, kp = r & 63;
    const float* W = (l == 0) ? W1 : ((l == 1) ? W2 : W3);
    float a = W[(2 * kp) * HDIM + n];
    float b = W[(2 * kp + 1) * HDIM + n];
    float ah = __bfloat162float(__float2bfloat16_rn(a));
    float bh = __bfloat162float(__float2bfloat16_rn(b));
    __nv_bfloat162 hp = __floats2bfloat162_rn(a, b);
    __nv_bfloat162 lp = __floats2bfloat162_rn(a - ah, b - bh);
    g_wth[l][n * 64 + kp] = *(uint32_t*)&hp;
    g_wtl[l][n * 64 + kp] = *(uint32_t*)&lp;
}

// ---------------- HMMA helper ----------------
__device__ __forceinline__ void mma_bf16(float* c, const uint32_t* a, uint32_t b0, uint32_t b1) {
    asm volatile("mma.sync.aligned.m16n8k16.row.col.f32.bf16.bf16.f32 "
                 "{%0,%1,%2,%3}, {%4,%5,%6,%7}, {%8,%9}, {%0,%1,%2,%3};"
                 : "+f"(c[0]), "+f"(c[1]), "+f"(c[2]), "+f"(c[3])
                 : "r"(a[0]), "r"(a[1]), "r"(a[2]), "r"(a[3]), "r"(b0), "r"(b1));
}

// smem (u32 units): M=128 A tile hi/lo only, stride 68; B comes from L1/global
#define SROW 68
#define SA_HI 0
#define SA_LO (128 * SROW)
#define GSMEM_BYTES (2 * 128 * SROW * 4)

__device__ __forceinline__ void split2(float x, float y, uint32_t& hi, uint32_t& lo) {
    float xh = __bfloat162float(__float2bfloat16_rn(x));
    float yh = __bfloat162float(__float2bfloat16_rn(y));
    __nv_bfloat162 hp = __floats2bfloat162_rn(x, y);
    __nv_bfloat162 lp = __floats2bfloat162_rn(x - xh, y - yh);
    hi = *(uint32_t*)&hp;
    lo = *(uint32_t*)&lp;
}

// ---------------- GEMM: g_tmp(fp16) = A @ W_layer, M=128, B via L1 ----------------
__global__ __launch_bounds__(256, 2) void k_gemm(const float* __restrict__ Aext,
                                                 int layer, int nrows) {
    extern __shared__ uint32_t sm[];
    const float* A = Aext ? Aext : g_h;
    int tid = threadIdx.x;
    int rowbase = blockIdx.x * 128;

    // A: load fp32, split to bf16 hi/lo in smem
#pragma unroll
    for (int it = 0; it < 32; it++) {
        int idx = tid + it * 256;           // 0..8191
        int row = idx >> 6, kp = idx & 63;
        int r = min(rowbase + row, nrows - 1);
        float2 v = *(const float2*)&A[(size_t)r * HDIM + kp * 2];
        uint32_t hi, lo;
        split2(v.x, v.y, hi, lo);
        sm[SA_HI + row * SROW + kp] = hi;
        sm[SA_LO + row * SROW + kp] = lo;
    }
    __syncthreads();

    int lane = tid & 31, warp = tid >> 5;
    int g = lane >> 2, tig = lane & 3;
    int m0 = (warp >> 1) * 32;
    int n0 = (warp & 1) * 64;

    const uint32_t* __restrict__ wth = g_wth[layer];
    const uint32_t* __restrict__ wtl = g_wtl[layer];

    float acc[2][8][4];
#pragma unroll
    for (int i = 0; i < 2; i++)
#pragma unroll
        for (int j = 0; j < 8; j++)
#pragma unroll
            for (int q = 0; q < 4; q++) acc[i][j][q] = 0.f;

#pragma unroll 1
    for (int s = 0; s < 8; s++) {
        int kb = s * 8;
        uint32_t ah[2][4], al[2][4];
#pragma unroll
        for (int i = 0; i < 2; i++) {
            int rb = m0 + i * 16;
            int o0 = (rb + g) * SROW + kb + tig;
            int o1 = (rb + 8 + g) * SROW + kb + tig;
            ah[i][0] = sm[SA_HI + o0]; ah[i][1] = sm[SA_HI + o1];
            ah[i][2] = sm[SA_HI + o0 + 4]; ah[i][3] = sm[SA_HI + o1 + 4];
            al[i][0] = sm[SA_LO + o0]; al[i][1] = sm[SA_LO + o1];
            al[i][2] = sm[SA_LO + o0 + 4]; al[i][3] = sm[SA_LO + o1 + 4];
        }
#pragma unroll
        for (int j = 0; j < 8; j++) {
            int nn = n0 + j * 8 + g;
            int ob = nn * 64 + s * 8 + tig;           // kp index, same mapping as R8 smem
            uint32_t bh0 = __ldg(&wth[ob]), bh1 = __ldg(&wth[ob + 4]);
            uint32_t bl0 = __ldg(&wtl[ob]), bl1 = __ldg(&wtl[ob + 4]);
#pragma unroll
            for (int i = 0; i < 2; i++) {
                mma_bf16(acc[i][j], ah[i], bh0, bh1);
                mma_bf16(acc[i][j], ah[i], bl0, bl1);
                mma_bf16(acc[i][j], al[i], bh0, bh1);
            }
        }
    }

    // epilogue: fp16 g_tmp
#pragma unroll
    for (int i = 0; i < 2; i++) {
#pragma unroll
        for (int j = 0; j < 8; j++) {
            int r0 = rowbase + m0 + i * 16 + g;
            int c = n0 + j * 8 + tig * 2;
            if (r0 < nrows) {
                __half2 h = __floats2half2_rn(acc[i][j][0], acc[i][j][1]);
                *(__half2*)&g_tmp[(size_t)r0 * HDIM + c] = h;
            }
            if (r0 + 8 < nrows) {
                __half2 h = __floats2half2_rn(acc[i][j][2], acc[i][j][3]);
                *(__half2*)&g_tmp[(size_t)(r0 + 8) * HDIM + c] = h;
            }
        }
    }
}

// ---------------- aggregation: g_h = relu(D^-1/2 A D^-1/2 * g_tmp + b) ----------------
__global__ __launch_bounds__(256) void k_agg(const float* __restrict__ bias, int n) {
    int warp = threadIdx.x >> 5, lane = threadIdx.x & 31;
    int node = blockIdx.x * 8 + warp;
    if (node >= n) return;
    float4 acc = make_float4(0.f, 0.f, 0.f, 0.f);
    int beg = g_ptr[node], end = g_ptr[node + 1];
#pragma unroll 4
    for (int p = beg; p < end; p++) {
        int s = g_csrc[p];
        float ds = g_dinv[s];
        uint2 raw = *(const uint2*)&g_tmp[(size_t)s * HDIM + lane * 4];
        float2 v0 = __half22float2(*(__half2*)&raw.x);
        float2 v1 = __half22float2(*(__half2*)&raw.y);
        acc.x += ds * v0.x; acc.y += ds * v0.y;
        acc.z += ds * v1.x; acc.w += ds * v1.y;
    }
    float di = g_dinv[node];
    float di2 = di * di;
    uint2 sraw = *(const uint2*)&g_tmp[(size_t)node * HDIM + lane * 4];
    float2 s0 = __half22float2(*(__half2*)&sraw.x);
    float2 s1 = __half22float2(*(__half2*)&sraw.y);
    float4 b = ((const float4*)bias)[lane];
    float4 r;
    r.x = fmaxf(di * acc.x + di2 * s0.x + b.x, 0.f);
    r.y = fmaxf(di * acc.y + di2 * s0.y + b.y, 0.f);
    r.z = fmaxf(di * acc.z + di2 * s1.x + b.z, 0.f);
    r.w = fmaxf(di * acc.w + di2 * s1.y + b.w, 0.f);
    ((float4*)g_h)[(size_t)node * 32 + lane] = r;
}

// ---------------- pooling ----------------
#define PCHUNK 64
__global__ __launch_bounds__(128) void k_pool(const void* batch, int n) {
    int f = threadIdx.x;
    int n0 = blockIdx.x * PCHUNK;
    int n1 = min(n0 + PCHUNK, n);
    if (n0 >= n) return;
    int is64 = g_is64;
    int curg = loadIdx(batch, n0, is64);
    float acc = 0.f;
    for (int i = n0; i < n1; i++) {
        int g = loadIdx(batch, i, is64);
        if (g != curg) {
            atomicAdd(&g_pool[curg * HDIM + f], acc);
            acc = 0.f; curg = g;
        }
        acc += g_h[(size_t)i * HDIM + f];
    }
    atomicAdd(&g_pool[curg * HDIM + f], acc);
}

// ---------------- classifier ----------------
__global__ void k_cls(const float* __restrict__ Wl, const float* __restrict__ bl,
                      float* __restrict__ out) {
    int g = blockIdx.x;
    int lane = threadIdx.x;
    float invc = 1.0f / fmaxf(g_gcnt[g], 1.0f);
    float acc = (lane < CDIM) ? bl[lane] : 0.f;
    for (int k = 0; k < HDIM; k++) {
        float p = g_pool[g * HDIM + k] * invc;
        if (lane < CDIM) acc += p * Wl[k * CDIM + lane];
    }
    if (lane < CDIM) out[g * CDIM + lane] = acc;
}

// ---------------- launch ----------------
extern "C" void kernel_launch(void* const* d_in, const int* in_sizes, int n_in,
                              void* d_out, int out_size) {
    const float* x  = (const float*)d_in[0];
    const float* W1 = (const float*)d_in[1];
    const float* b1 = (const float*)d_in[2];
    const float* W2 = (const float*)d_in[3];
    const float* b2 = (const float*)d_in[4];
    const float* W3 = (const float*)d_in[5];
    const float* b3 = (const float*)d_in[6];
    const float* Wl = (const float*)d_in[7];
    const float* bl = (const float*)d_in[8];
    const void*  ei = d_in[9];
    const void*  bt = d_in[10];

    int N = in_sizes[0] / HDIM;
    int E = in_sizes[9] / 2;
    int G = out_size / CDIM;

    static cudaStream_t s_side = nullptr;
    static cudaEvent_t ev_fork = nullptr, ev_join = nullptr;
    if (!s_side) {
        cudaStreamCreateWithFlags(&s_side, cudaStreamNonBlocking);
        cudaEventCreateWithFlags(&ev_fork, cudaEventDisableTiming);
        cudaEventCreateWithFlags(&ev_join, cudaEventDisableTiming);
        cudaFuncSetAttribute(k_gemm, cudaFuncAttributeMaxDynamicSharedMemorySize, GSMEM_BYTES);
    }

    int nb = (N + 1023) / 1024;
    int mma_blocks = (N + 127) / 128;
    int agg_blocks = (N + 7) / 8;

    // fork: CSR prep on side stream; W split + GEMM1 on main
    cudaEventRecord(ev_fork, 0);
    cudaStreamWaitEvent(s_side, ev_fork, 0);

    k_init<<<(N + 255) / 256, 256, 0, s_side>>>(ei, N, G);
    k_deg<<<(E + 255) / 256, 256, 0, s_side>>>(ei, E);
    k_scan1<<<nb, 1024, 0, s_side>>>(N);
    k_scan23<<<nb, 1024, 0, s_side>>>(N, nb);
    k_fill<<<(E + 255) / 256, 256, 0, s_side>>>(ei, bt, E, N);
    cudaEventRecord(ev_join, s_side);

    k_wsplit<<<(3 * HDIM * 64 + 255) / 256, 256>>>(W1, W2, W3);
    k_gemm<<<mma_blocks, 256, GSMEM_BYTES>>>(x, 0, N);

    cudaStreamWaitEvent(0, ev_join, 0);

    k_agg<<<agg_blocks, 256>>>(b1, N);
    k_gemm<<<mma_blocks, 256, GSMEM_BYTES>>>(nullptr, 1, N);
    k_agg<<<agg_blocks, 256>>>(b2, N);
    k_gemm<<<mma_blocks, 256, GSMEM_BYTES>>>(nullptr, 2, N);
    k_agg<<<agg_blocks, 256>>>(b3, N);

    k_pool<<<(N + PCHUNK - 1) / PCHUNK, 128>>>(bt, N);
    k_cls<<<G, 32>>>(Wl, bl, (float*)d_out);
}

// round 14
// speedup vs baseline: 1.0700x; 1.0700x over previous
#include <cuda_runtime.h>
#include <cuda_fp16.h>
#include <cuda_bf16.h>
#include <cstdint>

#define HDIM 128
#define MAXN 50000
#define MAXE 600000
#define MAXG 128
#define CDIM 10

// ---------------- scratch (no allocations allowed) ----------------
__device__ int      g_is64;
__device__ int      g_cnt[MAXN];
__device__ float    g_dinv[MAXN];
__device__ int      g_ptr[MAXN + 1];
__device__ int      g_pos[MAXN];
__device__ int      g_csrc[MAXE];
__device__ int      g_bsum[128];
__device__ float    g_h[(size_t)MAXN * HDIM];
__device__ __half   g_tA[(size_t)MAXN * HDIM];
__device__ __half   g_tB[(size_t)MAXN * HDIM];
__device__ float    g_pool[MAXG * HDIM];
__device__ float    g_gcnt[MAXG];
__device__ uint32_t g_wth[3][HDIM * 64];   // W^T bf16-hi, packed k-pairs: [n][kp]
__device__ uint32_t g_wtl[3][HDIM * 64];   // W^T bf16-lo

__device__ __forceinline__ int loadIdx(const void* p, long long i, int is64) {
    if (is64) return (int)((const long long*)p)[i];
    return ((const int*)p)[i];
}

// ---------------- fused prep ----------------
__global__ void k_init(const void* ei, int n, int g) {
    int i = blockIdx.x * blockDim.x + threadIdx.x;
    if (i == 0) {
        const int* w = (const int*)ei;
        int all0 = 1;
        for (int j = 0; j < 32; j++) if (w[2 * j + 1] != 0) all0 = 0;
        g_is64 = all0;
    }
    if (i < n) g_cnt[i] = 0;
    if (i < g * HDIM) g_pool[i] = 0.f;
    if (i < g) g_gcnt[i] = 0.f;
}

__global__ void k_deg(const void* ei, int E) {
    int e = blockIdx.x * blockDim.x + threadIdx.x;
    if (e >= E) return;
    int d = loadIdx(ei, (long long)E + e, g_is64);
    atomicAdd(&g_cnt[d], 1);
}

__global__ void k_scan1(int n) {
    __shared__ int s[1024];
    int tid = threadIdx.x;
    int i = blockIdx.x * 1024 + tid;
    int v = (i < n) ? g_cnt[i] : 0;
    if (i < n) g_dinv[i] = rsqrtf((float)(v + 1));   // +1 = self-loop
    s[tid] = v;
    __syncthreads();
    for (int off = 1; off < 1024; off <<= 1) {
        int t = (tid >= off) ? s[tid - off] : 0;
        __syncthreads();
        s[tid] += t;
        __syncthreads();
    }
    if (i < n) g_ptr[i] = s[tid] - v;
    if (tid == 1023) g_bsum[blockIdx.x] = s[tid];
}

__global__ void k_scan23(int n, int nb) {
    __shared__ int carry;
    if (threadIdx.x == 0) {
        int acc = 0;
        for (int b = 0; b < blockIdx.x; b++) acc += g_bsum[b];
        carry = acc;
        if (blockIdx.x == nb - 1) g_ptr[n] = acc + g_bsum[nb - 1];
    }
    __syncthreads();
    int i = blockIdx.x * 1024 + threadIdx.x;
    if (i < n) {
        int p = g_ptr[i] + carry;
        g_ptr[i] = p;
        g_pos[i] = p;
    }
}

__global__ void k_fill(const void* ei, const void* batch, int E, int n) {
    int e = blockIdx.x * blockDim.x + threadIdx.x;
    if (e >= E) return;
    int is64 = g_is64;
    int s = loadIdx(ei, e, is64);
    int d = loadIdx(ei, (long long)E + e, is64);
    int p = atomicAdd(&g_pos[d], 1);
    g_csrc[p] = s;
    if (e < n) {
        int g = loadIdx(batch, e, is64);
        atomicAdd(&g_gcnt[g], 1.0f);
    }
}

// ---------------- W split/transpose ----------------
__global__ void k_wsplit(const float* __restrict__ W1, const float* __restrict__ W2,
                         const float* __restrict__ W3) {
    int i = blockIdx.x * blockDim.x + threadIdx.x;
    if (i >= 3 * HDIM * 64) return;
    int l = i >> 13, r = i & 8191;
    int n = r >> 6, kp = r & 63;
    const float* W = (l == 0) ? W1 : ((l == 1) ? W2 : W3);
    float a = W[(2 * kp) * HDIM + n];
    float b = W[(2 * kp + 1) * HDIM + n];
    float ah = __bfloat162float(__float2bfloat16_rn(a));
    float bh = __bfloat162float(__float2bfloat16_rn(b));
    __nv_bfloat162 hp = __floats2bfloat162_rn(a, b);
    __nv_bfloat162 lp = __floats2bfloat162_rn(a - ah, b - bh);
    g_wth[l][n * 64 + kp] = *(uint32_t*)&hp;
    g_wtl[l][n * 64 + kp] = *(uint32_t*)&lp;
}

// ---------------- HMMA helper ----------------
__device__ __forceinline__ void mma_bf16(float* c, const uint32_t* a, uint32_t b0, uint32_t b1) {
    asm volatile("mma.sync.aligned.m16n8k16.row.col.f32.bf16.bf16.f32 "
                 "{%0,%1,%2,%3}, {%4,%5,%6,%7}, {%8,%9}, {%0,%1,%2,%3};"
                 : "+f"(c[0]), "+f"(c[1]), "+f"(c[2]), "+f"(c[3])
                 : "r"(a[0]), "r"(a[1]), "r"(a[2]), "r"(a[3]), "r"(b0), "r"(b1));
}

// smem layout (u32 units): M=128 A tile hi/lo + full B hi/lo, stride 68 (R8-proven)
#define SROW 68
#define SA_HI 0
#define SA_LO (128 * SROW)
#define SB_HI (2 * 128 * SROW)
#define SB_LO (3 * 128 * SROW)
#define GSMEM_BYTES (4 * 128 * SROW * 4)

__device__ __forceinline__ void split2(float x, float y, uint32_t& hi, uint32_t& lo) {
    float xh = __bfloat162float(__float2bfloat16_rn(x));
    float yh = __bfloat162float(__float2bfloat16_rn(y));
    __nv_bfloat162 hp = __floats2bfloat162_rn(x, y);
    __nv_bfloat162 lp = __floats2bfloat162_rn(x - xh, y - yh);
    hi = *(uint32_t*)&hp;
    lo = *(uint32_t*)&lp;
}

// ---------------- GEMM (R8 kernel + block offset): dst(fp16) = A @ W_layer ----------------
__global__ __launch_bounds__(256, 1) void k_gemm(const float* __restrict__ Aext,
                                                 __half* __restrict__ dst,
                                                 int layer, int blockoff, int nrows) {
    extern __shared__ uint32_t sm[];
    const float* A = Aext ? Aext : g_h;
    int tid = threadIdx.x;
    int rowbase = (blockIdx.x + blockoff) * 128;

    // B: pre-split W^T global -> smem
    {
        const uint32_t* wth = g_wth[layer];
        const uint32_t* wtl = g_wtl[layer];
#pragma unroll
        for (int it = 0; it < 32; it++) {
            int idx = tid + it * 256;
            int n = idx >> 6, kp = idx & 63;
            sm[SB_HI + n * SROW + kp] = wth[idx];
            sm[SB_LO + n * SROW + kp] = wtl[idx];
        }
    }
    // A: load fp32, split to bf16 hi/lo
#pragma unroll
    for (int it = 0; it < 32; it++) {
        int idx = tid + it * 256;
        int row = idx >> 6, kp = idx & 63;
        int r = min(rowbase + row, nrows - 1);
        float2 v = *(const float2*)&A[(size_t)r * HDIM + kp * 2];
        uint32_t hi, lo;
        split2(v.x, v.y, hi, lo);
        sm[SA_HI + row * SROW + kp] = hi;
        sm[SA_LO + row * SROW + kp] = lo;
    }
    __syncthreads();

    int lane = tid & 31, warp = tid >> 5;
    int g = lane >> 2, tig = lane & 3;
    int m0 = (warp >> 1) * 32;
    int n0 = (warp & 1) * 64;

    float acc[2][8][4];
#pragma unroll
    for (int i = 0; i < 2; i++)
#pragma unroll
        for (int j = 0; j < 8; j++)
#pragma unroll
            for (int q = 0; q < 4; q++) acc[i][j][q] = 0.f;

#pragma unroll 1
    for (int s = 0; s < 8; s++) {
        int kb = s * 8;
        uint32_t ah[2][4], al[2][4];
#pragma unroll
        for (int i = 0; i < 2; i++) {
            int rb = m0 + i * 16;
            int o0 = (rb + g) * SROW + kb + tig;
            int o1 = (rb + 8 + g) * SROW + kb + tig;
            ah[i][0] = sm[SA_HI + o0]; ah[i][1] = sm[SA_HI + o1];
            ah[i][2] = sm[SA_HI + o0 + 4]; ah[i][3] = sm[SA_HI + o1 + 4];
            al[i][0] = sm[SA_LO + o0]; al[i][1] = sm[SA_LO + o1];
            al[i][2] = sm[SA_LO + o0 + 4]; al[i][3] = sm[SA_LO + o1 + 4];
        }
#pragma unroll
        for (int j = 0; j < 8; j++) {
            int nn = n0 + j * 8 + g;
            int ob = nn * SROW + kb + tig;
            uint32_t bh0 = sm[SB_HI + ob], bh1 = sm[SB_HI + ob + 4];
            uint32_t bl0 = sm[SB_LO + ob], bl1 = sm[SB_LO + ob + 4];
#pragma unroll
            for (int i = 0; i < 2; i++) {
                mma_bf16(acc[i][j], ah[i], bh0, bh1);
                mma_bf16(acc[i][j], ah[i], bl0, bl1);
                mma_bf16(acc[i][j], al[i], bh0, bh1);
            }
        }
    }

#pragma unroll
    for (int i = 0; i < 2; i++) {
#pragma unroll
        for (int j = 0; j < 8; j++) {
            int r0 = rowbase + m0 + i * 16 + g;
            int c = n0 + j * 8 + tig * 2;
            if (r0 < nrows) {
                __half2 h = __floats2half2_rn(acc[i][j][0], acc[i][j][1]);
                *(__half2*)&dst[(size_t)r0 * HDIM + c] = h;
            }
            if (r0 + 8 < nrows) {
                __half2 h = __floats2half2_rn(acc[i][j][2], acc[i][j][3]);
                *(__half2*)&dst[(size_t)(r0 + 8) * HDIM + c] = h;
            }
        }
    }
}

// ---------------- aggregation (node-ranged): g_h = relu(Ahat * src + b) ----------------
__global__ __launch_bounds__(256) void k_agg(const __half* __restrict__ src,
                                             const float* __restrict__ bias,
                                             int node0, int nend) {
    int warp = threadIdx.x >> 5, lane = threadIdx.x & 31;
    int node = node0 + blockIdx.x * 8 + warp;
    if (node >= nend) return;
    float4 acc = make_float4(0.f, 0.f, 0.f, 0.f);
    int beg = g_ptr[node], end = g_ptr[node + 1];
#pragma unroll 4
    for (int p = beg; p < end; p++) {
        int s = g_csrc[p];
        float ds = g_dinv[s];
        uint2 raw = *(const uint2*)&src[(size_t)s * HDIM + lane * 4];
        float2 v0 = __half22float2(*(__half2*)&raw.x);
        float2 v1 = __half22float2(*(__half2*)&raw.y);
        acc.x += ds * v0.x; acc.y += ds * v0.y;
        acc.z += ds * v1.x; acc.w += ds * v1.y;
    }
    float di = g_dinv[node];
    float di2 = di * di;
    uint2 sraw = *(const uint2*)&src[(size_t)node * HDIM + lane * 4];
    float2 s0 = __half22float2(*(__half2*)&sraw.x);
    float2 s1 = __half22float2(*(__half2*)&sraw.y);
    float4 b = ((const float4*)bias)[lane];
    float4 r;
    r.x = fmaxf(di * acc.x + di2 * s0.x + b.x, 0.f);
    r.y = fmaxf(di * acc.y + di2 * s0.y + b.y, 0.f);
    r.z = fmaxf(di * acc.z + di2 * s1.x + b.z, 0.f);
    r.w = fmaxf(di * acc.w + di2 * s1.y + b.w, 0.f);
    ((float4*)g_h)[(size_t)node * 32 + lane] = r;
}

// ---------------- pooling (node-ranged) ----------------
#define PCHUNK 64
__global__ __launch_bounds__(128) void k_pool(const void* batch, int node0, int nend) {
    int f = threadIdx.x;
    int n0 = node0 + blockIdx.x * PCHUNK;
    int n1 = min(n0 + PCHUNK, nend);
    if (n0 >= nend) return;
    int is64 = g_is64;
    int curg = loadIdx(batch, n0, is64);
    float acc = 0.f;
    for (int i = n0; i < n1; i++) {
        int g = loadIdx(batch, i, is64);
        if (g != curg) {
            atomicAdd(&g_pool[curg * HDIM + f], acc);
            acc = 0.f; curg = g;
        }
        acc += g_h[(size_t)i * HDIM + f];
    }
    atomicAdd(&g_pool[curg * HDIM + f], acc);
}

// ---------------- classifier ----------------
__global__ void k_cls(const float* __restrict__ Wl, const float* __restrict__ bl,
                      float* __restrict__ out) {
    int g = blockIdx.x;
    int lane = threadIdx.x;
    float invc = 1.0f / fmaxf(g_gcnt[g], 1.0f);
    float acc = (lane < CDIM) ? bl[lane] : 0.f;
    for (int k = 0; k < HDIM; k++) {
        float p = g_pool[g * HDIM + k] * invc;
        if (lane < CDIM) acc += p * Wl[k * CDIM + lane];
    }
    if (lane < CDIM) out[g * CDIM + lane] = acc;
}

// ---------------- launch: chunked agg/gemm pipeline across 3 streams ----------------
extern "C" void kernel_launch(void* const* d_in, const int* in_sizes, int n_in,
                              void* d_out, int out_size) {
    const float* x  = (const float*)d_in[0];
    const float* W1 = (const float*)d_in[1];
    const float* b1 = (const float*)d_in[2];
    const float* W2 = (const float*)d_in[3];
    const float* b2 = (const float*)d_in[4];
    const float* W3 = (const float*)d_in[5];
    const float* b3 = (const float*)d_in[6];
    const float* Wl = (const float*)d_in[7];
    const float* bl = (const float*)d_in[8];
    const void*  ei = d_in[9];
    const void*  bt = d_in[10];

    int N = in_sizes[0] / HDIM;
    int E = in_sizes[9] / 2;
    int G = out_size / CDIM;

    static cudaStream_t sG = nullptr, sA = nullptr;   // 2nd gemm stream, agg stream
    static cudaEvent_t ev[14];
    if (!sG) {
        cudaStreamCreateWithFlags(&sG, cudaStreamNonBlocking);
        cudaStreamCreateWithFlags(&sA, cudaStreamNonBlocking);
        for (int i = 0; i < 14; i++) cudaEventCreateWithFlags(&ev[i], cudaEventDisableTiming);
        cudaFuncSetAttribute(k_gemm, cudaFuncAttributeMaxDynamicSharedMemorySize, GSMEM_BYTES);
    }
    static __half *p_tA = nullptr, *p_tB = nullptr;
    if (!p_tA) {
        cudaGetSymbolAddress((void**)&p_tA, g_tA);
        cudaGetSymbolAddress((void**)&p_tB, g_tB);
    }
    // event ids
    enum { EV_FORK, EV_G1, EV_A1C0, EV_A1C1, EV_G2C0, EV_G2C1,
           EV_A2C0, EV_A2C1, EV_G3C0, EV_G3C1, EV_A3C0, EV_A3C1, EV_G2C1D, EV_G3C1D };

    int nb = (N + 1023) / 1024;
    int mma_blocks = (N + 127) / 128;        // 391
    int c0b = (mma_blocks + 1) / 2;          // 196 gemm blocks in chunk 0
    int c1b = mma_blocks - c0b;              // 195
    int split = c0b * 128;                   // node split point (25088)
    int aggb0 = (split + 7) / 8;
    int aggb1 = (N - split + 7) / 8;
    int poolb0 = (split + PCHUNK - 1) / PCHUNK;
    int poolb1 = (N - split + PCHUNK - 1) / PCHUNK;

    // ---- stream sA: CSR prep, then chunked aggs ----
    cudaEventRecord(ev[EV_FORK], 0);
    cudaStreamWaitEvent(sA, ev[EV_FORK], 0);
    k_init<<<(N + 255) / 256, 256, 0, sA>>>(ei, N, G);
    k_deg<<<(E + 255) / 256, 256, 0, sA>>>(ei, E);
    k_scan1<<<nb, 1024, 0, sA>>>(N);
    k_scan23<<<nb, 1024, 0, sA>>>(N, nb);
    k_fill<<<(E + 255) / 256, 256, 0, sA>>>(ei, bt, E, N);

    // ---- main: W split + gemm1 (all rows) -> tA ----
    k_wsplit<<<(3 * HDIM * 64 + 255) / 256, 256>>>(W1, W2, W3);
    k_gemm<<<mma_blocks, 256, GSMEM_BYTES>>>(x, p_tA, 0, 0, N);
    cudaEventRecord(ev[EV_G1], 0);

    // ---- sA: agg1 chunks (reads tA) ----
    cudaStreamWaitEvent(sA, ev[EV_G1], 0);
    k_agg<<<aggb0, 256, 0, sA>>>(p_tA, b1, 0, split);
    cudaEventRecord(ev[EV_A1C0], sA);
    k_agg<<<aggb1, 256, 0, sA>>>(p_tA, b1, split, N);
    cudaEventRecord(ev[EV_A1C1], sA);

    // ---- gemm2 chunks -> tB (main: c0, sG: c1) ----
    cudaStreamWaitEvent(0, ev[EV_A1C0], 0);
    k_gemm<<<c0b, 256, GSMEM_BYTES>>>(nullptr, p_tB, 1, 0, N);
    cudaEventRecord(ev[EV_G2C0], 0);
    cudaStreamWaitEvent(sG, ev[EV_A1C1], 0);
    k_gemm<<<c1b, 256, GSMEM_BYTES, sG>>>(nullptr, p_tB, 1, c0b, N);
    cudaEventRecord(ev[EV_G2C1], sG);

    // ---- sA: agg2 chunks (reads tB) ----
    cudaStreamWaitEvent(sA, ev[EV_G2C0], 0);
    cudaStreamWaitEvent(sA, ev[EV_G2C1], 0);
    k_agg<<<aggb0, 256, 0, sA>>>(p_tB, b2, 0, split);
    cudaEventRecord(ev[EV_A2C0], sA);
    k_agg<<<aggb1, 256, 0, sA>>>(p_tB, b2, split, N);
    cudaEventRecord(ev[EV_A2C1], sA);

    // ---- gemm3 chunks -> tA ----
    cudaStreamWaitEvent(0, ev[EV_A2C0], 0);
    k_gemm<<<c0b, 256, GSMEM_BYTES>>>(nullptr, p_tA, 2, 0, N);
    cudaEventRecord(ev[EV_G3C0], 0);
    cudaStreamWaitEvent(sG, ev[EV_A2C1], 0);
    k_gemm<<<c1b, 256, GSMEM_BYTES, sG>>>(nullptr, p_tA, 2, c0b, N);
    cudaEventRecord(ev[EV_G3C1], sG);

    // ---- sA: agg3 chunks (reads tA, writes g_h) ----
    cudaStreamWaitEvent(sA, ev[EV_G3C0], 0);
    cudaStreamWaitEvent(sA, ev[EV_G3C1], 0);
    k_agg<<<aggb0, 256, 0, sA>>>(p_tA, b3, 0, split);
    cudaEventRecord(ev[EV_A3C0], sA);
    k_agg<<<aggb1, 256, 0, sA>>>(p_tA, b3, split, N);
    cudaEventRecord(ev[EV_A3C1], sA);

    // ---- main: pool chunks + classifier ----
    cudaStreamWaitEvent(0, ev[EV_A3C0], 0);
    k_pool<<<poolb0, 128>>>(bt, 0, split);
    cudaStreamWaitEvent(0, ev[EV_A3C1], 0);
    k_pool<<<poolb1, 128>>>(bt, split, N);
    k_cls<<<G, 32>>>(Wl, bl, (float*)d_out);
}

// round 15
// speedup vs baseline: 1.1586x; 1.0828x over previous
#include <cuda_runtime.h>
#include <cuda_fp16.h>
#include <cuda_bf16.h>
#include <cstdint>

#define HDIM 128
#define MAXN 50000
#define MAXE 600000
#define MAXG 128
#define CDIM 10

// ---------------- scratch (no allocations allowed) ----------------
__device__ int      g_is64;
__device__ int      g_cnt[MAXN];
__device__ float    g_dinv[MAXN];
__device__ int      g_ptr[MAXN + 1];
__device__ int      g_pos[MAXN];
__device__ int      g_csrc[MAXE];
__device__ int      g_bsum[128];
__device__ float    g_h[(size_t)MAXN * HDIM];
__device__ __half   g_tmp[(size_t)MAXN * HDIM];
__device__ float    g_pool[MAXG * HDIM];
__device__ float    g_gcnt[MAXG];
__device__ uint32_t g_wth[3][HDIM * 64];   // W^T bf16-hi, packed k-pairs: [n][kp]
__device__ uint32_t g_wtl[3][HDIM * 64];   // W^T bf16-lo

__device__ __forceinline__ int loadIdx(const void* p, long long i, int is64) {
    if (is64) return (int)((const long long*)p)[i];
    return ((const int*)p)[i];
}

// ---------------- fused prep ----------------
__global__ void k_init(const void* ei, int n, int g) {
    int i = blockIdx.x * blockDim.x + threadIdx.x;
    if (i == 0) {
        const int* w = (const int*)ei;
        int all0 = 1;
        for (int j = 0; j < 32; j++) if (w[2 * j + 1] != 0) all0 = 0;
        g_is64 = all0;
    }
    if (i < n) g_cnt[i] = 0;
    if (i < g * HDIM) g_pool[i] = 0.f;
    if (i < g) g_gcnt[i] = 0.f;
}

__global__ void k_deg(const void* ei, int E) {
    int e = blockIdx.x * blockDim.x + threadIdx.x;
    if (e >= E) return;
    int d = loadIdx(ei, (long long)E + e, g_is64);
    atomicAdd(&g_cnt[d], 1);
}

__global__ void k_scan1(int n) {
    __shared__ int s[1024];
    int tid = threadIdx.x;
    int i = blockIdx.x * 1024 + tid;
    int v = (i < n) ? g_cnt[i] : 0;
    if (i < n) g_dinv[i] = rsqrtf((float)(v + 1));   // +1 = self-loop
    s[tid] = v;
    __syncthreads();
    for (int off = 1; off < 1024; off <<= 1) {
        int t = (tid >= off) ? s[tid - off] : 0;
        __syncthreads();
        s[tid] += t;
        __syncthreads();
    }
    if (i < n) g_ptr[i] = s[tid] - v;
    if (tid == 1023) g_bsum[blockIdx.x] = s[tid];
}

__global__ void k_scan23(int n, int nb) {
    __shared__ int carry;
    if (threadIdx.x == 0) {
        int acc = 0;
        for (int b = 0; b < blockIdx.x; b++) acc += g_bsum[b];
        carry = acc;
        if (blockIdx.x == nb - 1) g_ptr[n] = acc + g_bsum[nb - 1];
    }
    __syncthreads();
    int i = blockIdx.x * 1024 + threadIdx.x;
    if (i < n) {
        int p = g_ptr[i] + carry;
        g_ptr[i] = p;
        g_pos[i] = p;
    }
}

__global__ void k_fill(const void* ei, const void* batch, int E, int n) {
    int e = blockIdx.x * blockDim.x + threadIdx.x;
    if (e >= E) return;
    int is64 = g_is64;
    int s = loadIdx(ei, e, is64);
    int d = loadIdx(ei, (long long)E + e, is64);
    int p = atomicAdd(&g_pos[d], 1);
    g_csrc[p] = s;
    if (e < n) {
        int g = loadIdx(batch, e, is64);
        atomicAdd(&g_gcnt[g], 1.0f);
    }
}

// ---------------- W split/transpose ----------------
__global__ void k_wsplit(const float* __restrict__ W1, const float* __restrict__ W2,
                         const float* __restrict__ W3) {
    int i = blockIdx.x * blockDim.x + threadIdx.x;
    if (i >= 3 * HDIM * 64) return;
    int l = i >> 13, r = i & 8191;
    int n = r >> 6, kp = r & 63;
    const float* W = (l == 0) ? W1 : ((l == 1) ? W2 : W3);
    float a = W[(2 * kp) * HDIM + n];
    float b = W[(2 * kp + 1) * HDIM + n];
    float ah = __bfloat162float(__float2bfloat16_rn(a));
    float bh = __bfloat162float(__float2bfloat16_rn(b));
    __nv_bfloat162 hp = __floats2bfloat162_rn(a, b);
    __nv_bfloat162 lp = __floats2bfloat162_rn(a - ah, b - bh);
    g_wth[l][n * 64 + kp] = *(uint32_t*)&hp;
    g_wtl[l][n * 64 + kp] = *(uint32_t*)&lp;
}

// ---------------- HMMA helper ----------------
__device__ __forceinline__ void mma_bf16(float* c, const uint32_t* a, uint32_t b0, uint32_t b1) {
    asm volatile("mma.sync.aligned.m16n8k16.row.col.f32.bf16.bf16.f32 "
                 "{%0,%1,%2,%3}, {%4,%5,%6,%7}, {%8,%9}, {%0,%1,%2,%3};"
                 : "+f"(c[0]), "+f"(c[1]), "+f"(c[2]), "+f"(c[3])
                 : "r"(a[0]), "r"(a[1]), "r"(a[2]), "r"(a[3]), "r"(b0), "r"(b1));
}

// ---------------- cp.async helpers ----------------
__device__ __forceinline__ void cp_async8(uint32_t saddr, const void* g) {
    asm volatile("cp.async.ca.shared.global [%0], [%1], 8;" :: "r"(saddr), "l"(g) : "memory");
}
#define CP_COMMIT() asm volatile("cp.async.commit_group;" ::: "memory")
#define CP_WAIT0()  asm volatile("cp.async.wait_group 0;" ::: "memory")

// smem layout (u32 units): A split hi/lo + B hi/lo (stride 68) + raw A staging
#define SROW 68
#define SA_HI 0
#define SA_LO (128 * SROW)                  // 8704
#define SB_HI (2 * 128 * SROW)              // 17408
#define SB_LO (3 * 128 * SROW)              // 26112
#define RAW   (4 * 128 * SROW)              // 34816
#define GSMEM_BYTES ((4 * 128 * SROW + 128 * 128) * 4)   // 204800 B

__device__ __forceinline__ void split2(float x, float y, uint32_t& hi, uint32_t& lo) {
    float xh = __bfloat162float(__float2bfloat16_rn(x));
    float yh = __bfloat162float(__float2bfloat16_rn(y));
    __nv_bfloat162 hp = __floats2bfloat162_rn(x, y);
    __nv_bfloat162 lp = __floats2bfloat162_rn(x - xh, y - yh);
    hi = *(uint32_t*)&hp;
    lo = *(uint32_t*)&lp;
}

// ---------------- persistent GEMM: g_tmp(fp16) = A @ W_layer ----------------
__global__ __launch_bounds__(256, 1) void k_gemm(const float* __restrict__ Aext,
                                                 int layer, int nrows, int ntiles) {
    extern __shared__ uint32_t sm[];
    const float* A = Aext ? Aext : g_h;
    int tid = threadIdx.x;
    uint32_t raw_base = (uint32_t)__cvta_generic_to_shared(&sm[RAW]);

    // B: pre-split W^T global -> smem, once per block
    {
        const uint32_t* wth = g_wth[layer];
        const uint32_t* wtl = g_wtl[layer];
#pragma unroll
        for (int it = 0; it < 32; it++) {
            int idx = tid + it * 256;
            int n = idx >> 6, kp = idx & 63;
            sm[SB_HI + n * SROW + kp] = wth[idx];
            sm[SB_LO + n * SROW + kp] = wtl[idx];
        }
    }

    // prologue: stage tile0 raw A via cp.async
    int t0 = blockIdx.x;
    {
        int rowbase = t0 * 128;
#pragma unroll
        for (int it = 0; it < 32; it++) {
            int idx = tid + it * 256;
            int row = idx >> 6, kp2 = (idx & 63) * 2;
            int r = min(rowbase + row, nrows - 1);
            cp_async8(raw_base + (uint32_t)(row * 128 + kp2) * 4, &A[(size_t)r * HDIM + kp2]);
        }
        CP_COMMIT();
        CP_WAIT0();
        __syncthreads();
        // convert raw -> split
#pragma unroll
        for (int it = 0; it < 32; it++) {
            int idx = tid + it * 256;
            int row = idx >> 6, kp = idx & 63;
            float2 v = *(const float2*)&sm[RAW + row * 128 + kp * 2];
            uint32_t hi, lo;
            split2(v.x, v.y, hi, lo);
            sm[SA_HI + row * SROW + kp] = hi;
            sm[SA_LO + row * SROW + kp] = lo;
        }
        __syncthreads();
    }

    int lane = tid & 31, warp = tid >> 5;
    int g = lane >> 2, tig = lane & 3;
    int m0 = (warp >> 1) * 32;
    int n0 = (warp & 1) * 64;

    for (int t = t0; t < ntiles; t += gridDim.x) {
        int tn = t + gridDim.x;
        // prefetch next tile's raw A during MMA
        if (tn < ntiles) {
            int rowbase = tn * 128;
#pragma unroll
            for (int it = 0; it < 32; it++) {
                int idx = tid + it * 256;
                int row = idx >> 6, kp2 = (idx & 63) * 2;
                int r = min(rowbase + row, nrows - 1);
                cp_async8(raw_base + (uint32_t)(row * 128 + kp2) * 4, &A[(size_t)r * HDIM + kp2]);
            }
            CP_COMMIT();
        }

        // ---- MMA phase (R8-proven mapping) ----
        int rowbase = t * 128;
        float acc[2][8][4];
#pragma unroll
        for (int i = 0; i < 2; i++)
#pragma unroll
            for (int j = 0; j < 8; j++)
#pragma unroll
                for (int q = 0; q < 4; q++) acc[i][j][q] = 0.f;

#pragma unroll 1
        for (int s = 0; s < 8; s++) {
            int kb = s * 8;
            uint32_t ah[2][4], al[2][4];
#pragma unroll
            for (int i = 0; i < 2; i++) {
                int rb = m0 + i * 16;
                int o0 = (rb + g) * SROW + kb + tig;
                int o1 = (rb + 8 + g) * SROW + kb + tig;
                ah[i][0] = sm[SA_HI + o0]; ah[i][1] = sm[SA_HI + o1];
                ah[i][2] = sm[SA_HI + o0 + 4]; ah[i][3] = sm[SA_HI + o1 + 4];
                al[i][0] = sm[SA_LO + o0]; al[i][1] = sm[SA_LO + o1];
                al[i][2] = sm[SA_LO + o0 + 4]; al[i][3] = sm[SA_LO + o1 + 4];
            }
#pragma unroll
            for (int j = 0; j < 8; j++) {
                int nn = n0 + j * 8 + g;
                int ob = nn * SROW + kb + tig;
                uint32_t bh0 = sm[SB_HI + ob], bh1 = sm[SB_HI + ob + 4];
                uint32_t bl0 = sm[SB_LO + ob], bl1 = sm[SB_LO + ob + 4];
#pragma unroll
                for (int i = 0; i < 2; i++) {
                    mma_bf16(acc[i][j], ah[i], bh0, bh1);
                    mma_bf16(acc[i][j], ah[i], bl0, bl1);
                    mma_bf16(acc[i][j], al[i], bh0, bh1);
                }
            }
        }

        // epilogue: fp16 g_tmp
#pragma unroll
        for (int i = 0; i < 2; i++) {
#pragma unroll
            for (int j = 0; j < 8; j++) {
                int r0 = rowbase + m0 + i * 16 + g;
                int c = n0 + j * 8 + tig * 2;
                if (r0 < nrows) {
                    __half2 h = __floats2half2_rn(acc[i][j][0], acc[i][j][1]);
                    *(__half2*)&g_tmp[(size_t)r0 * HDIM + c] = h;
                }
                if (r0 + 8 < nrows) {
                    __half2 h = __floats2half2_rn(acc[i][j][2], acc[i][j][3]);
                    *(__half2*)&g_tmp[(size_t)(r0 + 8) * HDIM + c] = h;
                }
            }
        }

        __syncthreads();   // all warps done reading split buffers
        if (tn < ntiles) {
            CP_WAIT0();
            __syncthreads();   // raw staged
#pragma unroll
            for (int it = 0; it < 32; it++) {
                int idx = tid + it * 256;
                int row = idx >> 6, kp = idx & 63;
                float2 v = *(const float2*)&sm[RAW + row * 128 + kp * 2];
                uint32_t hi, lo;
                split2(v.x, v.y, hi, lo);
                sm[SA_HI + row * SROW + kp] = hi;
                sm[SA_LO + row * SROW + kp] = lo;
            }
            __syncthreads();
        }
    }
}

// ---------------- aggregation: g_h = relu(D^-1/2 A D^-1/2 * g_tmp + b) ----------------
__global__ __launch_bounds__(256) void k_agg(const float* __restrict__ bias, int n) {
    int warp = threadIdx.x >> 5, lane = threadIdx.x & 31;
    int node = blockIdx.x * 8 + warp;
    if (node >= n) return;
    float4 acc = make_float4(0.f, 0.f, 0.f, 0.f);
    int beg = g_ptr[node], end = g_ptr[node + 1];
#pragma unroll 4
    for (int p = beg; p < end; p++) {
        int s = g_csrc[p];
        float ds = g_dinv[s];
        uint2 raw = *(const uint2*)&g_tmp[(size_t)s * HDIM + lane * 4];
        float2 v0 = __half22float2(*(__half2*)&raw.x);
        float2 v1 = __half22float2(*(__half2*)&raw.y);
        acc.x += ds * v0.x; acc.y += ds * v0.y;
        acc.z += ds * v1.x; acc.w += ds * v1.y;
    }
    float di = g_dinv[node];
    float di2 = di * di;
    uint2 sraw = *(const uint2*)&g_tmp[(size_t)node * HDIM + lane * 4];
    float2 s0 = __half22float2(*(__half2*)&sraw.x);
    float2 s1 = __half22float2(*(__half2*)&sraw.y);
    float4 b = ((const float4*)bias)[lane];
    float4 r;
    r.x = fmaxf(di * acc.x + di2 * s0.x + b.x, 0.f);
    r.y = fmaxf(di * acc.y + di2 * s0.y + b.y, 0.f);
    r.z = fmaxf(di * acc.z + di2 * s1.x + b.z, 0.f);
    r.w = fmaxf(di * acc.w + di2 * s1.y + b.w, 0.f);
    ((float4*)g_h)[(size_t)node * 32 + lane] = r;
}

// ---------------- pooling ----------------
#define PCHUNK 64
__global__ __launch_bounds__(128) void k_pool(const void* batch, int n) {
    int f = threadIdx.x;
    int n0 = blockIdx.x * PCHUNK;
    int n1 = min(n0 + PCHUNK, n);
    if (n0 >= n) return;
    int is64 = g_is64;
    int curg = loadIdx(batch, n0, is64);
    float acc = 0.f;
    for (int i = n0; i < n1; i++) {
        int g = loadIdx(batch, i, is64);
        if (g != curg) {
            atomicAdd(&g_pool[curg * HDIM + f], acc);
            acc = 0.f; curg = g;
        }
        acc += g_h[(size_t)i * HDIM + f];
    }
    atomicAdd(&g_pool[curg * HDIM + f], acc);
}

// ---------------- classifier ----------------
__global__ void k_cls(const float* __restrict__ Wl, const float* __restrict__ bl,
                      float* __restrict__ out) {
    int g = blockIdx.x;
    int lane = threadIdx.x;
    float invc = 1.0f / fmaxf(g_gcnt[g], 1.0f);
    float acc = (lane < CDIM) ? bl[lane] : 0.f;
    for (int k = 0; k < HDIM; k++) {
        float p = g_pool[g * HDIM + k] * invc;
        if (lane < CDIM) acc += p * Wl[k * CDIM + lane];
    }
    if (lane < CDIM) out[g * CDIM + lane] = acc;
}

// ---------------- launch (R8 serial schedule + persistent GEMM) ----------------
extern "C" void kernel_launch(void* const* d_in, const int* in_sizes, int n_in,
                              void* d_out, int out_size) {
    const float* x  = (const float*)d_in[0];
    const float* W1 = (const float*)d_in[1];
    const float* b1 = (const float*)d_in[2];
    const float* W2 = (const float*)d_in[3];
    const float* b2 = (const float*)d_in[4];
    const float* W3 = (const float*)d_in[5];
    const float* b3 = (const float*)d_in[6];
    const float* Wl = (const float*)d_in[7];
    const float* bl = (const float*)d_in[8];
    const void*  ei = d_in[9];
    const void*  bt = d_in[10];

    int N = in_sizes[0] / HDIM;
    int E = in_sizes[9] / 2;
    int G = out_size / CDIM;

    static cudaStream_t s_side = nullptr;
    static cudaEvent_t ev_fork = nullptr, ev_join = nullptr;
    static int n_sm = 148;
    if (!s_side) {
        cudaStreamCreateWithFlags(&s_side, cudaStreamNonBlocking);
        cudaEventCreateWithFlags(&ev_fork, cudaEventDisableTiming);
        cudaEventCreateWithFlags(&ev_join, cudaEventDisableTiming);
        cudaFuncSetAttribute(k_gemm, cudaFuncAttributeMaxDynamicSharedMemorySize, GSMEM_BYTES);
        cudaDeviceProp prop;
        cudaGetDeviceProperties(&prop, 0);
        n_sm = prop.multiProcessorCount;
    }

    int nb = (N + 1023) / 1024;
    int ntiles = (N + 127) / 128;
    int gemm_grid = (ntiles < n_sm) ? ntiles : n_sm;
    int agg_blocks = (N + 7) / 8;

    // fork: CSR prep on side stream; W split + GEMM1 on main
    cudaEventRecord(ev_fork, 0);
    cudaStreamWaitEvent(s_side, ev_fork, 0);

    k_init<<<(N + 255) / 256, 256, 0, s_side>>>(ei, N, G);
    k_deg<<<(E + 255) / 256, 256, 0, s_side>>>(ei, E);
    k_scan1<<<nb, 1024, 0, s_side>>>(N);
    k_scan23<<<nb, 1024, 0, s_side>>>(N, nb);
    k_fill<<<(E + 255) / 256, 256, 0, s_side>>>(ei, bt, E, N);
    cudaEventRecord(ev_join, s_side);

    k_wsplit<<<(3 * HDIM * 64 + 255) / 256, 256>>>(W1, W2, W3);
    k_gemm<<<gemm_grid, 256, GSMEM_BYTES>>>(x, 0, N, ntiles);

    cudaStreamWaitEvent(0, ev_join, 0);

    k_agg<<<agg_blocks, 256>>>(b1, N);
    k_gemm<<<gemm_grid, 256, GSMEM_BYTES>>>(nullptr, 1, N, ntiles);
    k_agg<<<agg_blocks, 256>>>(b2, N);
    k_gemm<<<gemm_grid, 256, GSMEM_BYTES>>>(nullptr, 2, N, ntiles);
    k_agg<<<agg_blocks, 256>>>(b3, N);

    k_pool<<<(N + PCHUNK - 1) / PCHUNK, 128>>>(bt, N);
    k_cls<<<G, 32>>>(Wl, bl, (float*)d_out);
}

// round 16
// speedup vs baseline: 1.3206x; 1.1399x over previous
#include <cuda_runtime.h>
#include <cuda_fp16.h>
#include <cstdint>

#define HDIM 128
#define MAXN 50000
#define MAXE 600000
#define MAXG 128
#define CDIM 10

// ---------------- scratch (no allocations allowed) ----------------
__device__ int      g_is64;
__device__ int      g_cnt[MAXN];
__device__ float    g_dinv[MAXN];
__device__ int      g_ptr[MAXN + 1];
__device__ int      g_pos[MAXN];
__device__ int      g_csrc[MAXE];
__device__ int      g_bsum[128];
__device__ __half   g_h[(size_t)MAXN * HDIM];     // fp16 activations
__device__ __half   g_tmp[(size_t)MAXN * HDIM];   // fp16 gemm output
__device__ float    g_pool[MAXG * HDIM];
__device__ float    g_gcnt[MAXG];
__device__ uint32_t g_wth[3][HDIM * 64];   // W^T fp16-hi, packed k-pairs: [n][kp]
__device__ uint32_t g_wtl[3][HDIM * 64];   // W^T fp16-lo

__device__ __forceinline__ int loadIdx(const void* p, long long i, int is64) {
    if (is64) return (int)((const long long*)p)[i];
    return ((const int*)p)[i];
}

// ---------------- fused prep ----------------
__global__ void k_init(const void* ei, int n, int g) {
    int i = blockIdx.x * blockDim.x + threadIdx.x;
    if (i == 0) {
        const int* w = (const int*)ei;
        int all0 = 1;
        for (int j = 0; j < 32; j++) if (w[2 * j + 1] != 0) all0 = 0;
        g_is64 = all0;
    }
    if (i < n) g_cnt[i] = 0;
    if (i < g * HDIM) g_pool[i] = 0.f;
    if (i < g) g_gcnt[i] = 0.f;
}

__global__ void k_deg(const void* ei, int E) {
    int e = blockIdx.x * blockDim.x + threadIdx.x;
    if (e >= E) return;
    int d = loadIdx(ei, (long long)E + e, g_is64);
    atomicAdd(&g_cnt[d], 1);
}

__global__ void k_scan1(int n) {
    __shared__ int s[1024];
    int tid = threadIdx.x;
    int i = blockIdx.x * 1024 + tid;
    int v = (i < n) ? g_cnt[i] : 0;
    if (i < n) g_dinv[i] = rsqrtf((float)(v + 1));   // +1 = self-loop
    s[tid] = v;
    __syncthreads();
    for (int off = 1; off < 1024; off <<= 1) {
        int t = (tid >= off) ? s[tid - off] : 0;
        __syncthreads();
        s[tid] += t;
        __syncthreads();
    }
    if (i < n) g_ptr[i] = s[tid] - v;
    if (tid == 1023) g_bsum[blockIdx.x] = s[tid];
}

__global__ void k_scan23(int n, int nb) {
    __shared__ int carry;
    if (threadIdx.x == 0) {
        int acc = 0;
        for (int b = 0; b < blockIdx.x; b++) acc += g_bsum[b];
        carry = acc;
        if (blockIdx.x == nb - 1) g_ptr[n] = acc + g_bsum[nb - 1];
    }
    __syncthreads();
    int i = blockIdx.x * 1024 + threadIdx.x;
    if (i < n) {
        int p = g_ptr[i] + carry;
        g_ptr[i] = p;
        g_pos[i] = p;
    }
}

__global__ void k_fill(const void* ei, const void* batch, int E, int n) {
    int e = blockIdx.x * blockDim.x + threadIdx.x;
    if (e >= E) return;
    int is64 = g_is64;
    int s = loadIdx(ei, e, is64);
    int d = loadIdx(ei, (long long)E + e, is64);
    int p = atomicAdd(&g_pos[d], 1);
    g_csrc[p] = s;
    if (e < n) {
        int g = loadIdx(batch, e, is64);
        atomicAdd(&g_gcnt[g], 1.0f);
    }
}

// ---------------- W split/transpose (fp16 hi/lo) ----------------
__global__ void k_wsplit(const float* __restrict__ W1, const float* __restrict__ W2,
                         const float* __restrict__ W3) {
    int i = blockIdx.x * blockDim.x + threadIdx.x;
    if (i >= 3 * HDIM * 64) return;
    int l = i >> 13, r = i & 8191;
    int n = r >> 6, kp = r & 63;
    const float* W = (l == 0) ? W1 : ((l == 1) ? W2 : W3);
    float a = W[(2 * kp) * HDIM + n];
    float b = W[(2 * kp + 1) * HDIM + n];
    __half ah = __float2half_rn(a);
    __half bh = __float2half_rn(b);
    __half al = __float2half_rn(a - __half2float(ah));
    __half bl = __float2half_rn(b - __half2float(bh));
    __half2 hp = __halves2half2(ah, bh);
    __half2 lp = __halves2half2(al, bl);
    g_wth[l][n * 64 + kp] = *(uint32_t*)&hp;
    g_wtl[l][n * 64 + kp] = *(uint32_t*)&lp;
}

// ---------------- HMMA helper (fp16) ----------------
__device__ __forceinline__ void mma_f16(float* c, const uint32_t* a, uint32_t b0, uint32_t b1) {
    asm volatile("mma.sync.aligned.m16n8k16.row.col.f32.f16.f16.f32 "
                 "{%0,%1,%2,%3}, {%4,%5,%6,%7}, {%8,%9}, {%0,%1,%2,%3};"
                 : "+f"(c[0]), "+f"(c[1]), "+f"(c[2]), "+f"(c[3])
                 : "r"(a[0]), "r"(a[1]), "r"(a[2]), "r"(a[3]), "r"(b0), "r"(b1));
}

// smem layout (u32 units): A fp16 + B hi/lo fp16, stride 68
#define SROW 68
#define SA    0
#define SB_HI (128 * SROW)
#define SB_LO (2 * 128 * SROW)
#define GSMEM_BYTES (3 * 128 * SROW * 4)   // 104448 B -> 2 CTAs/SM

// ---------------- GEMM: g_tmp(fp16) = A @ W_layer (A fp16, W fp16-split) ----------------
__global__ __launch_bounds__(256, 2) void k_gemm(const float* __restrict__ Aext,
                                                 int layer, int nrows) {
    extern __shared__ uint32_t sm[];
    int tid = threadIdx.x;
    int rowbase = blockIdx.x * 128;

    // B: pre-split W^T global -> smem
    {
        const uint32_t* wth = g_wth[layer];
        const uint32_t* wtl = g_wtl[layer];
#pragma unroll
        for (int it = 0; it < 32; it++) {
            int idx = tid + it * 256;
            int n = idx >> 6, kp = idx & 63;
            sm[SB_HI + n * SROW + kp] = wth[idx];
            sm[SB_LO + n * SROW + kp] = wtl[idx];
        }
    }
    // A: layer 0 converts fp32 x -> fp16; layers 1-2 copy fp16 g_h words
    if (Aext) {
#pragma unroll
        for (int it = 0; it < 32; it++) {
            int idx = tid + it * 256;
            int row = idx >> 6, kp = idx & 63;
            int r = min(rowbase + row, nrows - 1);
            float2 v = *(const float2*)&Aext[(size_t)r * HDIM + kp * 2];
            __half2 h = __floats2half2_rn(v.x, v.y);
            sm[SA + row * SROW + kp] = *(uint32_t*)&h;
        }
    } else {
#pragma unroll
        for (int it = 0; it < 32; it++) {
            int idx = tid + it * 256;
            int row = idx >> 6, kp = idx & 63;
            int r = min(rowbase + row, nrows - 1);
            sm[SA + row * SROW + kp] = *(const uint32_t*)&g_h[(size_t)r * HDIM + kp * 2];
        }
    }
    __syncthreads();

    int lane = tid & 31, warp = tid >> 5;
    int g = lane >> 2, tig = lane & 3;
    int m0 = (warp >> 1) * 32;
    int n0 = (warp & 1) * 64;

    float acc[2][8][4];
#pragma unroll
    for (int i = 0; i < 2; i++)
#pragma unroll
        for (int j = 0; j < 8; j++)
#pragma unroll
            for (int q = 0; q < 4; q++) acc[i][j][q] = 0.f;

#pragma unroll 1
    for (int s = 0; s < 8; s++) {
        int kb = s * 8;
        uint32_t ah[2][4];
#pragma unroll
        for (int i = 0; i < 2; i++) {
            int rb = m0 + i * 16;
            int o0 = (rb + g) * SROW + kb + tig;
            int o1 = (rb + 8 + g) * SROW + kb + tig;
            ah[i][0] = sm[SA + o0]; ah[i][1] = sm[SA + o1];
            ah[i][2] = sm[SA + o0 + 4]; ah[i][3] = sm[SA + o1 + 4];
        }
#pragma unroll
        for (int j = 0; j < 8; j++) {
            int nn = n0 + j * 8 + g;
            int ob = nn * SROW + kb + tig;
            uint32_t bh0 = sm[SB_HI + ob], bh1 = sm[SB_HI + ob + 4];
            uint32_t bl0 = sm[SB_LO + ob], bl1 = sm[SB_LO + ob + 4];
#pragma unroll
            for (int i = 0; i < 2; i++) {
                mma_f16(acc[i][j], ah[i], bh0, bh1);
                mma_f16(acc[i][j], ah[i], bl0, bl1);
            }
        }
    }

    // epilogue: fp16 g_tmp
#pragma unroll
    for (int i = 0; i < 2; i++) {
#pragma unroll
        for (int j = 0; j < 8; j++) {
            int r0 = rowbase + m0 + i * 16 + g;
            int c = n0 + j * 8 + tig * 2;
            if (r0 < nrows) {
                __half2 h = __floats2half2_rn(acc[i][j][0], acc[i][j][1]);
                *(__half2*)&g_tmp[(size_t)r0 * HDIM + c] = h;
            }
            if (r0 + 8 < nrows) {
                __half2 h = __floats2half2_rn(acc[i][j][2], acc[i][j][3]);
                *(__half2*)&g_tmp[(size_t)(r0 + 8) * HDIM + c] = h;
            }
        }
    }
}

// ---------------- aggregation: g_h(fp16) = relu(D^-1/2 A D^-1/2 * g_tmp + b) ----------------
__global__ __launch_bounds__(256) void k_agg(const float* __restrict__ bias, int n) {
    int warp = threadIdx.x >> 5, lane = threadIdx.x & 31;
    int node = blockIdx.x * 8 + warp;
    if (node >= n) return;
    float4 acc = make_float4(0.f, 0.f, 0.f, 0.f);
    int beg = g_ptr[node], end = g_ptr[node + 1];
#pragma unroll 4
    for (int p = beg; p < end; p++) {
        int s = g_csrc[p];
        float ds = g_dinv[s];
        uint2 raw = *(const uint2*)&g_tmp[(size_t)s * HDIM + lane * 4];
        float2 v0 = __half22float2(*(__half2*)&raw.x);
        float2 v1 = __half22float2(*(__half2*)&raw.y);
        acc.x += ds * v0.x; acc.y += ds * v0.y;
        acc.z += ds * v1.x; acc.w += ds * v1.y;
    }
    float di = g_dinv[node];
    float di2 = di * di;
    uint2 sraw = *(const uint2*)&g_tmp[(size_t)node * HDIM + lane * 4];
    float2 s0 = __half22float2(*(__half2*)&sraw.x);
    float2 s1 = __half22float2(*(__half2*)&sraw.y);
    float4 b = ((const float4*)bias)[lane];
    float rx = fmaxf(di * acc.x + di2 * s0.x + b.x, 0.f);
    float ry = fmaxf(di * acc.y + di2 * s0.y + b.y, 0.f);
    float rz = fmaxf(di * acc.z + di2 * s1.x + b.z, 0.f);
    float rw = fmaxf(di * acc.w + di2 * s1.y + b.w, 0.f);
    uint2 o;
    __half2 h0 = __floats2half2_rn(rx, ry);
    __half2 h1 = __floats2half2_rn(rz, rw);
    o.x = *(uint32_t*)&h0; o.y = *(uint32_t*)&h1;
    *(uint2*)&g_h[(size_t)node * HDIM + lane * 4] = o;
}

// ---------------- pooling (reads fp16 g_h) ----------------
#define PCHUNK 64
__global__ __launch_bounds__(128) void k_pool(const void* batch, int n) {
    int f = threadIdx.x;
    int n0 = blockIdx.x * PCHUNK;
    int n1 = min(n0 + PCHUNK, n);
    if (n0 >= n) return;
    int is64 = g_is64;
    int curg = loadIdx(batch, n0, is64);
    float acc = 0.f;
    for (int i = n0; i < n1; i++) {
        int g = loadIdx(batch, i, is64);
        if (g != curg) {
            atomicAdd(&g_pool[curg * HDIM + f], acc);
            acc = 0.f; curg = g;
        }
        acc += __half2float(g_h[(size_t)i * HDIM + f]);
    }
    atomicAdd(&g_pool[curg * HDIM + f], acc);
}

// ---------------- classifier ----------------
__global__ void k_cls(const float* __restrict__ Wl, const float* __restrict__ bl,
                      float* __restrict__ out) {
    int g = blockIdx.x;
    int lane = threadIdx.x;
    float invc = 1.0f / fmaxf(g_gcnt[g], 1.0f);
    float acc = (lane < CDIM) ? bl[lane] : 0.f;
    for (int k = 0; k < HDIM; k++) {
        float p = g_pool[g * HDIM + k] * invc;
        if (lane < CDIM) acc += p * Wl[k * CDIM + lane];
    }
    if (lane < CDIM) out[g * CDIM + lane] = acc;
}

// ---------------- launch (R8 serial schedule) ----------------
extern "C" void kernel_launch(void* const* d_in, const int* in_sizes, int n_in,
                              void* d_out, int out_size) {
    const float* x  = (const float*)d_in[0];
    const float* W1 = (const float*)d_in[1];
    const float* b1 = (const float*)d_in[2];
    const float* W2 = (const float*)d_in[3];
    const float* b2 = (const float*)d_in[4];
    const float* W3 = (const float*)d_in[5];
    const float* b3 = (const float*)d_in[6];
    const float* Wl = (const float*)d_in[7];
    const float* bl = (const float*)d_in[8];
    const void*  ei = d_in[9];
    const void*  bt = d_in[10];

    int N = in_sizes[0] / HDIM;
    int E = in_sizes[9] / 2;
    int G = out_size / CDIM;

    static cudaStream_t s_side = nullptr;
    static cudaEvent_t ev_fork = nullptr, ev_join = nullptr;
    if (!s_side) {
        cudaStreamCreateWithFlags(&s_side, cudaStreamNonBlocking);
        cudaEventCreateWithFlags(&ev_fork, cudaEventDisableTiming);
        cudaEventCreateWithFlags(&ev_join, cudaEventDisableTiming);
        cudaFuncSetAttribute(k_gemm, cudaFuncAttributeMaxDynamicSharedMemorySize, GSMEM_BYTES);
    }

    int nb = (N + 1023) / 1024;
    int mma_blocks = (N + 127) / 128;
    int agg_blocks = (N + 7) / 8;

    // fork: CSR prep on side stream; W split + GEMM1 on main
    cudaEventRecord(ev_fork, 0);
    cudaStreamWaitEvent(s_side, ev_fork, 0);

    k_init<<<(N + 255) / 256, 256, 0, s_side>>>(ei, N, G);
    k_deg<<<(E + 255) / 256, 256, 0, s_side>>>(ei, E);
    k_scan1<<<nb, 1024, 0, s_side>>>(N);
    k_scan23<<<nb, 1024, 0, s_side>>>(N, nb);
    k_fill<<<(E + 255) / 256, 256, 0, s_side>>>(ei, bt, E, N);
    cudaEventRecord(ev_join, s_side);

    k_wsplit<<<(3 * HDIM * 64 + 255) / 256, 256>>>(W1, W2, W3);
    k_gemm<<<mma_blocks, 256, GSMEM_BYTES>>>(x, 0, N);

    cudaStreamWaitEvent(0, ev_join, 0);

    k_agg<<<agg_blocks, 256>>>(b1, N);
    k_gemm<<<mma_blocks, 256, GSMEM_BYTES>>>(nullptr, 1, N);
    k_agg<<<agg_blocks, 256>>>(b2, N);
    k_gemm<<<mma_blocks, 256, GSMEM_BYTES>>>(nullptr, 2, N);
    k_agg<<<agg_blocks, 256>>>(b3, N);

    k_pool<<<(N + PCHUNK - 1) / PCHUNK, 128>>>(bt, N);
    k_cls<<<G, 32>>>(Wl, bl, (float*)d_out);
}